// round 2
// baseline (speedup 1.0000x reference)
#include <cuda_runtime.h>

// ---------------------------------------------------------------------------
// SCRN layer, restructured:
//   xc = x @ Wx^T + bx                 -> big GEMM (M=BT, N=C, K=IN)
//   c_t = 0.05 c_{t-1} + 0.95 xc_t    -> elementwise scan over T (h-independent!)
//   a  = c @ Uc^T                      -> big GEMM (M=BT, N=H, K=C)
//   h_t = tanh(a_t + h_{t-1} @ Vh^T)   -> persistent kernel, grid barriers
// d_out layout: out[B,T,H] | h_T[B,H] | c_T[B,C]
// ---------------------------------------------------------------------------

namespace {
constexpr int Bn  = 64;
constexpr int Tn  = 512;
constexpr int INn = 1024;
constexpr int Hn  = 1024;
constexpr int Cn  = 512;
constexpr int BT  = Bn * Tn;          // 32768
constexpr int GRID_R = 128;           // persistent CTAs for the recurrence
}

// Scratch via __device__ globals (allocation-free rule).
__device__ float    g_c[(size_t)BT * Cn];      // 64 MB : xc, then c (in place)
__device__ float    g_a[(size_t)BT * Hn];      // 128 MB: a = c @ Uc^T
__device__ float    g_part[16 * Bn * Hn];      // 4 MB  : per-step K-split partials
__device__ unsigned g_bar;                     // grid-barrier counter

// ---------------------------------------------------------------------------
// NT GEMM: C[m][n] = sum_k A[m][k]*B[n][k] (+bias[n]).
// 128x128 block tile, BK=16, 256 threads, 8x8 micro-tile. Shapes divide evenly.
// ---------------------------------------------------------------------------
template<int N, int K, bool BIAS>
__global__ void __launch_bounds__(256) gemm_nt(const float* __restrict__ A,
                                               const float* __restrict__ Bm,
                                               const float* __restrict__ bias,
                                               float* __restrict__ C)
{
    __shared__ float As[16][132];
    __shared__ float Bs[16][132];
    const int tid = threadIdx.x;
    const int tx = tid & 15;
    const int ty = tid >> 4;
    const int m0 = blockIdx.y << 7;
    const int n0 = blockIdx.x << 7;
    const int lr = tid >> 2;          // 0..63
    const int lk = (tid & 3) << 2;    // 0,4,8,12

    const float* Ap = A  + (size_t)(m0 + lr) * K + lk;
    const float* Bp = Bm + (size_t)(n0 + lr) * K + lk;

    float acc[8][8];
#pragma unroll
    for (int i = 0; i < 8; ++i)
#pragma unroll
        for (int j = 0; j < 8; ++j) acc[i][j] = 0.f;

    for (int k0 = 0; k0 < K; k0 += 16) {
        float4 a0 = *(const float4*)(Ap + k0);
        float4 a1 = *(const float4*)(Ap + (size_t)64 * K + k0);
        float4 b0 = *(const float4*)(Bp + k0);
        float4 b1 = *(const float4*)(Bp + (size_t)64 * K + k0);
        As[lk + 0][lr]      = a0.x; As[lk + 1][lr]      = a0.y;
        As[lk + 2][lr]      = a0.z; As[lk + 3][lr]      = a0.w;
        As[lk + 0][lr + 64] = a1.x; As[lk + 1][lr + 64] = a1.y;
        As[lk + 2][lr + 64] = a1.z; As[lk + 3][lr + 64] = a1.w;
        Bs[lk + 0][lr]      = b0.x; Bs[lk + 1][lr]      = b0.y;
        Bs[lk + 2][lr]      = b0.z; Bs[lk + 3][lr]      = b0.w;
        Bs[lk + 0][lr + 64] = b1.x; Bs[lk + 1][lr + 64] = b1.y;
        Bs[lk + 2][lr + 64] = b1.z; Bs[lk + 3][lr + 64] = b1.w;
        __syncthreads();
#pragma unroll
        for (int kk = 0; kk < 16; ++kk) {
            float4 av0 = *(const float4*)&As[kk][ty * 8];
            float4 av1 = *(const float4*)&As[kk][ty * 8 + 4];
            float4 bv0 = *(const float4*)&Bs[kk][tx * 8];
            float4 bv1 = *(const float4*)&Bs[kk][tx * 8 + 4];
            float a[8] = {av0.x, av0.y, av0.z, av0.w, av1.x, av1.y, av1.z, av1.w};
            float b[8] = {bv0.x, bv0.y, bv0.z, bv0.w, bv1.x, bv1.y, bv1.z, bv1.w};
#pragma unroll
            for (int i = 0; i < 8; ++i)
#pragma unroll
                for (int j = 0; j < 8; ++j) acc[i][j] = fmaf(a[i], b[j], acc[i][j]);
        }
        __syncthreads();
    }

    float bv[8];
#pragma unroll
    for (int j = 0; j < 8; ++j) bv[j] = BIAS ? bias[n0 + tx * 8 + j] : 0.f;

#pragma unroll
    for (int i = 0; i < 8; ++i) {
        float* Cp = C + (size_t)(m0 + ty * 8 + i) * N + n0 + tx * 8;
        *(float4*)Cp       = make_float4(acc[i][0] + bv[0], acc[i][1] + bv[1],
                                         acc[i][2] + bv[2], acc[i][3] + bv[3]);
        *(float4*)(Cp + 4) = make_float4(acc[i][4] + bv[4], acc[i][5] + bv[5],
                                         acc[i][6] + bv[6], acc[i][7] + bv[7]);
    }
}

// ---------------------------------------------------------------------------
// Scan: c_t = 0.05 c_{t-1} + 0.95 xc_t, in place in g_c. Writes c_T.
// One thread per (b, channel): 32768 threads; loads coalesced across channels.
// ---------------------------------------------------------------------------
__global__ void __launch_bounds__(256) scan_kernel(const float* __restrict__ c0,
                                                   float* __restrict__ out)
{
    const int idx = blockIdx.x * 256 + threadIdx.x;   // 0..32767
    const int b = idx >> 9;
    const int i = idx & 511;
    float c = c0[idx];
    float* p = g_c + (size_t)b * Tn * Cn + i;
#pragma unroll 4
    for (int t = 0; t < Tn; ++t) {
        float xv = p[(size_t)t * Cn];
        c = 0.05f * c + 0.95f * xv;
        p[(size_t)t * Cn] = c;
    }
    out[(size_t)BT * Hn + (size_t)Bn * Hn + idx] = c;   // c_T tail
}

// ---------------------------------------------------------------------------
// Grid barrier. GRID_R blocks are all co-resident (128 <= 148 SMs,
// 48KB static smem, 256 thr -> at least 1 CTA/SM). Monotonic counter.
// ---------------------------------------------------------------------------
__device__ __forceinline__ void gridbar(unsigned epoch)
{
    __threadfence();          // make this thread's prior stores visible
    __syncthreads();
    if (threadIdx.x == 0) {
        atomicAdd(&g_bar, 1u);
        const unsigned tgt = epoch * (unsigned)GRID_R;
        while (*(volatile unsigned*)&g_bar < tgt) { }
    }
    __syncthreads();
    __threadfence();          // acquire side
}

__global__ void reset_bar() { g_bar = 0u; }

// ---------------------------------------------------------------------------
// Serial recurrence: 128 persistent CTAs = 16 k-slices x 8 j-slices.
// Phase 1 (per CTA): partial[b][j] = sum_{k in slice} h_{t-1}[b][k]*Vh[j][k]
//                    for its 128-wide j range, all 64 b. -> g_part
// Phase 2 (all CTAs): reduce 16 partials + a_t, tanh, write h_t to out.
// Vh tile (128j x 64k = 32KB) stays in smem the whole kernel.
// ---------------------------------------------------------------------------
__global__ void __launch_bounds__(256, 1) recur_kernel(const float* __restrict__ h0,
                                                       const float* __restrict__ Vh,
                                                       float* __restrict__ out)
{
    __shared__ float v_s[64][128];   // [k-k0][j-j0], 32 KB, persistent
    __shared__ float h_s[64][64];    // [b][k-k0],    16 KB, per step

    const int tid = threadIdx.x;
    const int js = blockIdx.x & 7;      // j0 = js*128
    const int ks = blockIdx.x >> 3;     // k0 = ks*64
    const int j0 = js * 128;
    const int k0 = ks * 64;
    const int tx = tid & 15;            // j micro index (8 cols each)
    const int ty = tid >> 4;            // b micro index (4 rows each)

    // Load Vh tile transposed into v_s[k][j]. Once per kernel.
    {
        const int jj = tid >> 1;               // 0..127
        const int kb = (tid & 1) * 32;         // 0 or 32
        const float* src = Vh + (size_t)(j0 + jj) * Hn + k0 + kb;
#pragma unroll
        for (int p = 0; p < 8; ++p) {
            float4 v = *(const float4*)(src + p * 4);
            const int k = kb + p * 4;
            v_s[k + 0][jj] = v.x; v_s[k + 1][jj] = v.y;
            v_s[k + 2][jj] = v.z; v_s[k + 3][jj] = v.w;
        }
    }

    const int lb = tid >> 2;            // 0..63 : b for h-slice load
    const int lk = (tid & 3) * 16;      // 0,16,32,48
    const int o_base = blockIdx.x * 256 + tid;   // phase-2 output id

    unsigned epoch = 0;

    for (int t = 0; t < Tn; ++t) {
        // ---- load h_{t-1}[b][k0:k0+64) into h_s ----
        const float* hsrc = (t == 0)
            ? (h0 + (size_t)lb * Hn + k0 + lk)
            : (out + ((size_t)lb * Tn + (t - 1)) * Hn + k0 + lk);
        {
            float4* dst = (float4*)&h_s[lb][lk];
            dst[0] = *(const float4*)(hsrc + 0);
            dst[1] = *(const float4*)(hsrc + 4);
            dst[2] = *(const float4*)(hsrc + 8);
            dst[3] = *(const float4*)(hsrc + 12);
        }
        __syncthreads();

        // ---- phase 1: partial GEMM over the 64-wide k slice ----
        float acc[4][8];
#pragma unroll
        for (int i = 0; i < 4; ++i)
#pragma unroll
            for (int j = 0; j < 8; ++j) acc[i][j] = 0.f;

#pragma unroll 4
        for (int kk = 0; kk < 64; ++kk) {
            float a0 = h_s[ty * 4 + 0][kk];
            float a1 = h_s[ty * 4 + 1][kk];
            float a2 = h_s[ty * 4 + 2][kk];
            float a3 = h_s[ty * 4 + 3][kk];
            const float* br = &v_s[kk][tx * 8];
            float4 bv0 = *(const float4*)br;
            float4 bv1 = *(const float4*)(br + 4);
            float b[8] = {bv0.x, bv0.y, bv0.z, bv0.w, bv1.x, bv1.y, bv1.z, bv1.w};
#pragma unroll
            for (int j = 0; j < 8; ++j) {
                acc[0][j] = fmaf(a0, b[j], acc[0][j]);
                acc[1][j] = fmaf(a1, b[j], acc[1][j]);
                acc[2][j] = fmaf(a2, b[j], acc[2][j]);
                acc[3][j] = fmaf(a3, b[j], acc[3][j]);
            }
        }

        // store partials: g_part[(ks*64+b)*1024 + j0 + j]
#pragma unroll
        for (int i = 0; i < 4; ++i) {
            float* pp = g_part + ((size_t)(ks * 64 + ty * 4 + i) << 10) + j0 + tx * 8;
            *(float4*)pp       = make_float4(acc[i][0], acc[i][1], acc[i][2], acc[i][3]);
            *(float4*)(pp + 4) = make_float4(acc[i][4], acc[i][5], acc[i][6], acc[i][7]);
        }

        gridbar(++epoch);   // partials visible everywhere

        // ---- phase 2: reduce 16 partials + a_t, tanh, write h_t ----
#pragma unroll
        for (int r = 0; r < 2; ++r) {
            const int o = o_base + r * (GRID_R * 256);   // 0..65535
            const int b = o >> 10;
            const int j = o & 1023;
            float s = g_a[((size_t)b * Tn + t) * Hn + j];
#pragma unroll
            for (int kr = 0; kr < 16; ++kr)
                s += g_part[((size_t)(kr * 64 + b) << 10) + j];
            const float hv = tanhf(s);
            out[((size_t)b * Tn + t) * Hn + j] = hv;
            if (t == Tn - 1)
                out[(size_t)BT * Hn + (size_t)b * Hn + j] = hv;   // h_T tail
        }

        gridbar(++epoch);   // h_t visible before next step's loads
        __syncthreads();    // protect h_s reuse
    }
}

// ---------------------------------------------------------------------------
extern "C" void kernel_launch(void* const* d_in, const int* in_sizes, int n_in,
                              void* d_out, int out_size)
{
    const float* x   = (const float*)d_in[0];   // [B,T,IN]
    const float* h0  = (const float*)d_in[1];   // [B,H]
    const float* c0  = (const float*)d_in[2];   // [B,C]
    const float* Wx  = (const float*)d_in[3];   // [C,IN]
    const float* bx  = (const float*)d_in[4];   // [C]
    const float* Uc  = (const float*)d_in[5];   // [H,C]
    const float* Vh  = (const float*)d_in[6];   // [H,H]
    float* out = (float*)d_out;

    float* c_buf;  cudaGetSymbolAddress((void**)&c_buf,  g_c);
    float* a_buf;  cudaGetSymbolAddress((void**)&a_buf,  g_a);

    // 1) xc = x @ Wx^T + bx   (M=BT, N=C=512, K=IN=1024)
    {
        dim3 grid(Cn / 128, BT / 128);
        gemm_nt<Cn, INn, true><<<grid, 256>>>(x, Wx, bx, c_buf);
    }
    // 2) scan over T (in place in g_c), writes c_T tail of out
    scan_kernel<<<BT / 256, 256>>>(c0, out);
    // 3) a = c @ Uc^T   (M=BT, N=H=1024, K=C=512)
    {
        dim3 grid(Hn / 128, BT / 128);
        gemm_nt<Hn, Cn, false><<<grid, 256>>>(c_buf, Uc, nullptr, a_buf);
    }
    // 4) serial recurrence -> out[B,T,H] and h_T tail
    reset_bar<<<1, 1>>>();
    recur_kernel<<<GRID_R, 256>>>(h0, Vh, out);
}

// round 4
// speedup vs baseline: 1.0854x; 1.0854x over previous
#include <cuda_runtime.h>
#include <cuda_bf16.h>
#include <cstdint>

// ---------------------------------------------------------------------------
// SCRN layer:
//   xc = x @ Wx^T + bx              -> bf16x3 tensor-core GEMM (M=BT,N=C,K=IN)
//   c_t = 0.05 c_{t-1} + 0.95 xc_t -> scan over T, emits bf16 hi/mid splits
//   a  = c @ Uc^T                   -> bf16x3 tensor-core GEMM (M=BT,N=H,K=C)
//   h_t = tanh(a_t + h_{t-1} Vh^T)  -> persistent fp32 kernel, grid barriers
// d_out layout: out[B,T,H] | h_T[B,H] | c_T[B,C]
// ---------------------------------------------------------------------------

namespace {
constexpr int Bn  = 64;
constexpr int Tn  = 512;
constexpr int INn = 1024;
constexpr int Hn  = 1024;
constexpr int Cn  = 512;
constexpr int BT  = Bn * Tn;          // 32768
constexpr int GRID_R = 128;
constexpr int PADK = 24;              // smem row stride (elems) for 16-wide k tiles
}

// Scratch (__device__ globals; allocation-free rule).
__device__ float          g_c[(size_t)BT * Cn];        // xc fp32
__device__ float          g_a[(size_t)BT * Hn];        // a fp32
__device__ __nv_bfloat16  g_xh[(size_t)BT * INn];      // x splits
__device__ __nv_bfloat16  g_xm[(size_t)BT * INn];
__device__ __nv_bfloat16  g_ch[(size_t)BT * Cn];       // c splits
__device__ __nv_bfloat16  g_cm[(size_t)BT * Cn];
__device__ __nv_bfloat16  g_wxh[Cn * INn], g_wxm[Cn * INn];
__device__ __nv_bfloat16  g_uch[Hn * Cn],  g_ucm[Hn * Cn];
__device__ float          g_part[16 * Bn * Hn];
__device__ unsigned       g_bar;

// ---------------------------------------------------------------------------
// fp32 -> (bf16 hi, bf16 mid) split, vectorized x4.
// ---------------------------------------------------------------------------
__global__ void __launch_bounds__(256) split_kernel(const float* __restrict__ in,
                                                    __nv_bfloat16* __restrict__ hi,
                                                    __nv_bfloat16* __restrict__ mid,
                                                    int n4)
{
    int i = blockIdx.x * 256 + threadIdx.x;
    if (i >= n4) return;
    float4 v = ((const float4*)in)[i];
    __nv_bfloat16 h[4], m[4];
    float vv[4] = {v.x, v.y, v.z, v.w};
#pragma unroll
    for (int k = 0; k < 4; ++k) {
        h[k] = __float2bfloat16(vv[k]);
        m[k] = __float2bfloat16(vv[k] - __bfloat162float(h[k]));
    }
    ((__nv_bfloat162*)hi)[i * 2 + 0] = __nv_bfloat162(h[0], h[1]);
    ((__nv_bfloat162*)hi)[i * 2 + 1] = __nv_bfloat162(h[2], h[3]);
    ((__nv_bfloat162*)mid)[i * 2 + 0] = __nv_bfloat162(m[0], m[1]);
    ((__nv_bfloat162*)mid)[i * 2 + 1] = __nv_bfloat162(m[2], m[3]);
}

// ---------------------------------------------------------------------------
// PTX helpers
// ---------------------------------------------------------------------------
__device__ __forceinline__ void cp16(uint32_t s, const void* g) {
    asm volatile("cp.async.cg.shared.global [%0], [%1], 16;" :: "r"(s), "l"(g));
}
__device__ __forceinline__ void cp_commit() { asm volatile("cp.async.commit_group;"); }
template<int W> __device__ __forceinline__ void cp_wait() {
    asm volatile("cp.async.wait_group %0;" :: "n"(W));
}
__device__ __forceinline__ void ldsm4(uint32_t& r0, uint32_t& r1, uint32_t& r2,
                                      uint32_t& r3, uint32_t addr) {
    asm volatile("ldmatrix.sync.aligned.m8n8.x4.shared.b16 {%0,%1,%2,%3}, [%4];"
                 : "=r"(r0), "=r"(r1), "=r"(r2), "=r"(r3) : "r"(addr));
}
__device__ __forceinline__ void mma16816(float* c, const uint32_t* a, const uint32_t* b) {
    asm volatile("mma.sync.aligned.m16n8k16.row.col.f32.bf16.bf16.f32 "
                 "{%0,%1,%2,%3},{%4,%5,%6,%7},{%8,%9},{%0,%1,%2,%3};"
                 : "+f"(c[0]), "+f"(c[1]), "+f"(c[2]), "+f"(c[3])
                 : "r"(a[0]), "r"(a[1]), "r"(a[2]), "r"(a[3]), "r"(b[0]), "r"(b[1]));
}

// ---------------------------------------------------------------------------
// bf16x3 NT GEMM: C[m][n] = sum_k A[m][k]*B[n][k] (+bias[n]), fp32 result.
// A,B given as (hi, mid) bf16 pairs; D += Ah*Bh + Ah*Bm + Am*Bh.
// 128x128 CTA tile, BK=16, 256 threads (8 warps as 4Mx2N of 32x64 warp tiles).
// cp.async double-buffered smem.
// ---------------------------------------------------------------------------
template<int N, int K, bool BIAS>
__global__ void __launch_bounds__(256) gemm_bf16x3(
    const __nv_bfloat16* __restrict__ Ah, const __nv_bfloat16* __restrict__ Am,
    const __nv_bfloat16* __restrict__ Bh, const __nv_bfloat16* __restrict__ Bm,
    const float* __restrict__ bias, float* __restrict__ C)
{
    __shared__ __align__(16) __nv_bfloat16 sm[2][4][128 * PADK];  // 48 KB

    const int tid = threadIdx.x;
    const int lane = tid & 31, warp = tid >> 5;
    const int wm = warp >> 1, wn = warp & 1;          // warp tile: 32(M) x 64(N)
    const int m0 = blockIdx.y * 128, n0 = blockIdx.x * 128;

    // global->smem staging: each thread cps 16B from each of the 4 matrices
    const int grow = tid >> 1, ghalf = tid & 1;
    const __nv_bfloat16* gA0 = Ah + (size_t)(m0 + grow) * K + ghalf * 8;
    const __nv_bfloat16* gA1 = Am + (size_t)(m0 + grow) * K + ghalf * 8;
    const __nv_bfloat16* gB0 = Bh + (size_t)(n0 + grow) * K + ghalf * 8;
    const __nv_bfloat16* gB1 = Bm + (size_t)(n0 + grow) * K + ghalf * 8;

    const uint32_t smem0 = (uint32_t)__cvta_generic_to_shared(&sm[0][0][0]);
    constexpr uint32_t MATB = 128 * PADK * 2;   // bytes per matrix slab
    constexpr uint32_t STGB = 4 * MATB;         // bytes per stage
    const uint32_t s_st = smem0 + (grow * PADK + ghalf * 8) * 2;

    float acc[2][8][4];
#pragma unroll
    for (int i = 0; i < 2; ++i)
#pragma unroll
        for (int j = 0; j < 8; ++j)
#pragma unroll
            for (int k = 0; k < 4; ++k) acc[i][j][k] = 0.f;

    // ldmatrix per-lane addressing
    const int a_row = lane & 15, a_kc = (lane >> 4) * 8;
    const int b_n = (lane & 7) + ((lane >> 4) << 3), b_kc = ((lane >> 3) & 1) * 8;
    const uint32_t aoff = ((wm * 32 + a_row) * PADK + a_kc) * 2;
    const uint32_t boff = ((wn * 64 + b_n) * PADK + b_kc) * 2;

    constexpr int S = K / 16;

    // prologue: stage 0
    {
        cp16(s_st + 0 * STGB + 0 * MATB, gA0);
        cp16(s_st + 0 * STGB + 1 * MATB, gA1);
        cp16(s_st + 0 * STGB + 2 * MATB, gB0);
        cp16(s_st + 0 * STGB + 3 * MATB, gB1);
        cp_commit();
    }

    for (int ks = 0; ks < S; ++ks) {
        const int cur = ks & 1;
        if (ks + 1 < S) {
            const uint32_t b = s_st + ((ks + 1) & 1) * STGB;
            const int k0 = (ks + 1) * 16;
            cp16(b + 0 * MATB, gA0 + k0);
            cp16(b + 1 * MATB, gA1 + k0);
            cp16(b + 2 * MATB, gB0 + k0);
            cp16(b + 3 * MATB, gB1 + k0);
            cp_commit();
            cp_wait<1>();
        } else {
            cp_wait<0>();
        }
        __syncthreads();

        const uint32_t sb = smem0 + cur * STGB;
        uint32_t ah[2][4], am[2][4], bh[8][2], bm[8][2];
#pragma unroll
        for (int mf = 0; mf < 2; ++mf) {
            ldsm4(ah[mf][0], ah[mf][1], ah[mf][2], ah[mf][3],
                  sb + 0 * MATB + aoff + mf * 16 * PADK * 2);
            ldsm4(am[mf][0], am[mf][1], am[mf][2], am[mf][3],
                  sb + 1 * MATB + aoff + mf * 16 * PADK * 2);
        }
#pragma unroll
        for (int nq = 0; nq < 4; ++nq) {
            uint32_t r0, r1, r2, r3;
            ldsm4(r0, r1, r2, r3, sb + 2 * MATB + boff + nq * 16 * PADK * 2);
            bh[nq * 2][0] = r0; bh[nq * 2][1] = r1;
            bh[nq * 2 + 1][0] = r2; bh[nq * 2 + 1][1] = r3;
            ldsm4(r0, r1, r2, r3, sb + 3 * MATB + boff + nq * 16 * PADK * 2);
            bm[nq * 2][0] = r0; bm[nq * 2][1] = r1;
            bm[nq * 2 + 1][0] = r2; bm[nq * 2 + 1][1] = r3;
        }
#pragma unroll
        for (int mf = 0; mf < 2; ++mf)
#pragma unroll
            for (int nf = 0; nf < 8; ++nf) {
                mma16816(acc[mf][nf], ah[mf], bh[nf]);
                mma16816(acc[mf][nf], ah[mf], bm[nf]);
                mma16816(acc[mf][nf], am[mf], bh[nf]);
            }
        __syncthreads();
    }

    // epilogue
    const int r = lane >> 2, cg = (lane & 3) * 2;
#pragma unroll
    for (int mf = 0; mf < 2; ++mf)
#pragma unroll
        for (int nf = 0; nf < 8; ++nf) {
            const int m = m0 + wm * 32 + mf * 16 + r;
            const int n = n0 + wn * 64 + nf * 8 + cg;
            float b0 = BIAS ? bias[n] : 0.f;
            float b1 = BIAS ? bias[n + 1] : 0.f;
            *(float2*)(C + (size_t)m * N + n) =
                make_float2(acc[mf][nf][0] + b0, acc[mf][nf][1] + b1);
            *(float2*)(C + (size_t)(m + 8) * N + n) =
                make_float2(acc[mf][nf][2] + b0, acc[mf][nf][3] + b1);
        }
}

// ---------------------------------------------------------------------------
// Scan: c_t = 0.05 c_{t-1} + 0.95 xc_t; emits bf16 hi/mid splits of c, and c_T.
// ---------------------------------------------------------------------------
__global__ void __launch_bounds__(256) scan_kernel(const float* __restrict__ c0,
                                                   float* __restrict__ out)
{
    const int idx = blockIdx.x * 256 + threadIdx.x;   // 0..32767
    const int b = idx >> 9;
    const int i = idx & 511;
    float c = c0[idx];
    const float* p = g_c + (size_t)b * Tn * Cn + i;
    __nv_bfloat16* ph = g_ch + (size_t)b * Tn * Cn + i;
    __nv_bfloat16* pm = g_cm + (size_t)b * Tn * Cn + i;
#pragma unroll 4
    for (int t = 0; t < Tn; ++t) {
        const float xv = p[(size_t)t * Cn];
        c = 0.05f * c + 0.95f * xv;
        const __nv_bfloat16 h = __float2bfloat16(c);
        ph[(size_t)t * Cn] = h;
        pm[(size_t)t * Cn] = __float2bfloat16(c - __bfloat162float(h));
    }
    out[(size_t)BT * Hn + (size_t)Bn * Hn + idx] = c;   // c_T tail
}

// ---------------------------------------------------------------------------
// Grid barrier (128 co-resident CTAs)
// ---------------------------------------------------------------------------
__device__ __forceinline__ void gridbar(unsigned epoch)
{
    __threadfence();
    __syncthreads();
    if (threadIdx.x == 0) {
        atomicAdd(&g_bar, 1u);
        const unsigned tgt = epoch * (unsigned)GRID_R;
        while (*(volatile unsigned*)&g_bar < tgt) { }
    }
    __syncthreads();
    __threadfence();
}

__global__ void reset_bar() { g_bar = 0u; }

// ---------------------------------------------------------------------------
// Serial recurrence: 128 persistent CTAs = 16 k-slices x 8 j-slices.
// ---------------------------------------------------------------------------
__global__ void __launch_bounds__(256, 1) recur_kernel(const float* __restrict__ h0,
                                                       const float* __restrict__ Vh,
                                                       float* __restrict__ out)
{
    __shared__ float v_s[64][128];
    __shared__ float h_s[64][64];

    const int tid = threadIdx.x;
    const int js = blockIdx.x & 7;
    const int ks = blockIdx.x >> 3;
    const int j0 = js * 128;
    const int k0 = ks * 64;
    const int tx = tid & 15;
    const int ty = tid >> 4;

    {
        const int jj = tid >> 1;
        const int kb = (tid & 1) * 32;
        const float* src = Vh + (size_t)(j0 + jj) * Hn + k0 + kb;
#pragma unroll
        for (int p = 0; p < 8; ++p) {
            float4 v = *(const float4*)(src + p * 4);
            const int k = kb + p * 4;
            v_s[k + 0][jj] = v.x; v_s[k + 1][jj] = v.y;
            v_s[k + 2][jj] = v.z; v_s[k + 3][jj] = v.w;
        }
    }

    const int lb = tid >> 2;
    const int lk = (tid & 3) * 16;
    const int o_base = blockIdx.x * 256 + tid;

    unsigned epoch = 0;

    for (int t = 0; t < Tn; ++t) {
        const float* hsrc = (t == 0)
            ? (h0 + (size_t)lb * Hn + k0 + lk)
            : (out + ((size_t)lb * Tn + (t - 1)) * Hn + k0 + lk);
        {
            float4* dst = (float4*)&h_s[lb][lk];
            dst[0] = *(const float4*)(hsrc + 0);
            dst[1] = *(const float4*)(hsrc + 4);
            dst[2] = *(const float4*)(hsrc + 8);
            dst[3] = *(const float4*)(hsrc + 12);
        }
        __syncthreads();

        float acc[4][8];
#pragma unroll
        for (int i = 0; i < 4; ++i)
#pragma unroll
            for (int j = 0; j < 8; ++j) acc[i][j] = 0.f;

#pragma unroll 4
        for (int kk = 0; kk < 64; ++kk) {
            float a0 = h_s[ty * 4 + 0][kk];
            float a1 = h_s[ty * 4 + 1][kk];
            float a2 = h_s[ty * 4 + 2][kk];
            float a3 = h_s[ty * 4 + 3][kk];
            const float* br = &v_s[kk][tx * 8];
            float4 bv0 = *(const float4*)br;
            float4 bv1 = *(const float4*)(br + 4);
            float b[8] = {bv0.x, bv0.y, bv0.z, bv0.w, bv1.x, bv1.y, bv1.z, bv1.w};
#pragma unroll
            for (int j = 0; j < 8; ++j) {
                acc[0][j] = fmaf(a0, b[j], acc[0][j]);
                acc[1][j] = fmaf(a1, b[j], acc[1][j]);
                acc[2][j] = fmaf(a2, b[j], acc[2][j]);
                acc[3][j] = fmaf(a3, b[j], acc[3][j]);
            }
        }

#pragma unroll
        for (int i = 0; i < 4; ++i) {
            float* pp = g_part + ((size_t)(ks * 64 + ty * 4 + i) << 10) + j0 + tx * 8;
            *(float4*)pp       = make_float4(acc[i][0], acc[i][1], acc[i][2], acc[i][3]);
            *(float4*)(pp + 4) = make_float4(acc[i][4], acc[i][5], acc[i][6], acc[i][7]);
        }

        gridbar(++epoch);

#pragma unroll
        for (int r = 0; r < 2; ++r) {
            const int o = o_base + r * (GRID_R * 256);
            const int b = o >> 10;
            const int j = o & 1023;
            float s = g_a[((size_t)b * Tn + t) * Hn + j];
#pragma unroll
            for (int kr = 0; kr < 16; ++kr)
                s += g_part[((size_t)(kr * 64 + b) << 10) + j];
            const float hv = tanhf(s);
            out[((size_t)b * Tn + t) * Hn + j] = hv;
            if (t == Tn - 1)
                out[(size_t)BT * Hn + (size_t)b * Hn + j] = hv;
        }

        gridbar(++epoch);
        __syncthreads();
    }
}

// ---------------------------------------------------------------------------
extern "C" void kernel_launch(void* const* d_in, const int* in_sizes, int n_in,
                              void* d_out, int out_size)
{
    const float* x   = (const float*)d_in[0];   // [B,T,IN]
    const float* h0  = (const float*)d_in[1];   // [B,H]
    const float* c0  = (const float*)d_in[2];   // [B,C]
    const float* Wx  = (const float*)d_in[3];   // [C,IN]
    const float* bx  = (const float*)d_in[4];   // [C]
    const float* Uc  = (const float*)d_in[5];   // [H,C]
    const float* Vh  = (const float*)d_in[6];   // [H,H]
    float* out = (float*)d_out;

    float* c_buf;           cudaGetSymbolAddress((void**)&c_buf, g_c);
    float* a_buf;           cudaGetSymbolAddress((void**)&a_buf, g_a);
    __nv_bfloat16 *xh, *xm, *ch, *cm, *wxh, *wxm, *uch, *ucm;
    cudaGetSymbolAddress((void**)&xh,  g_xh);
    cudaGetSymbolAddress((void**)&xm,  g_xm);
    cudaGetSymbolAddress((void**)&ch,  g_ch);
    cudaGetSymbolAddress((void**)&cm,  g_cm);
    cudaGetSymbolAddress((void**)&wxh, g_wxh);
    cudaGetSymbolAddress((void**)&wxm, g_wxm);
    cudaGetSymbolAddress((void**)&uch, g_uch);
    cudaGetSymbolAddress((void**)&ucm, g_ucm);

    // 0) fp32 -> bf16 hi/mid splits
    {
        int n4 = (BT * INn) / 4;
        split_kernel<<<(n4 + 255) / 256, 256>>>(x, xh, xm, n4);
        n4 = (Cn * INn) / 4;
        split_kernel<<<(n4 + 255) / 256, 256>>>(Wx, wxh, wxm, n4);
        n4 = (Hn * Cn) / 4;
        split_kernel<<<(n4 + 255) / 256, 256>>>(Uc, uch, ucm, n4);
    }
    // 1) xc = x @ Wx^T + bx
    {
        dim3 grid(Cn / 128, BT / 128);
        gemm_bf16x3<Cn, INn, true><<<grid, 256>>>(xh, xm, wxh, wxm, bx, c_buf);
    }
    // 2) scan -> c splits (bf16) + c_T tail
    scan_kernel<<<BT / 256, 256>>>(c0, out);
    // 3) a = c @ Uc^T
    {
        dim3 grid(Hn / 128, BT / 128);
        gemm_bf16x3<Hn, Cn, false><<<grid, 256>>>(ch, cm, uch, ucm, nullptr, a_buf);
    }
    // 4) serial recurrence
    reset_bar<<<1, 1>>>();
    recur_kernel<<<GRID_R, 256>>>(h0, Vh, out);
}